// round 14
// baseline (speedup 1.0000x reference)
#include <cuda_runtime.h>
#include <cstdint>

// Problem constants (fixed-shape problem)
#define B_SZ   4
#define T_SEQ  2048
#define E_DIM  1024
#define NH     16
#define HD     64
#define M_TOT  (B_SZ * T_SEQ)   // 8192

// ---------------------------------------------------------------------------
// Scratch (allocation-free rule: __device__ globals)
// ---------------------------------------------------------------------------
__device__ float g_q[(size_t)M_TOT * E_DIM];    // [B,H,T,D] (tf32-rounded)
__device__ float g_k[(size_t)M_TOT * E_DIM];    // [B,H,T,D] (tf32-rounded)
__device__ float g_v[(size_t)M_TOT * E_DIM];    // [B,H,T,D] (tf32-rounded)
__device__ float g_ctx[(size_t)M_TOT * E_DIM];  // [B,T,E]   (tf32-rounded)
__device__ float g_x [(size_t)M_TOT * E_DIM];   // tf32-rounded copy of x
__device__ float g_wq[(size_t)E_DIM * E_DIM];   // tf32-rounded weights
__device__ float g_wk[(size_t)E_DIM * E_DIM];
__device__ float g_wv[(size_t)E_DIM * E_DIM];
__device__ float g_wo[(size_t)E_DIM * E_DIM];

// ---------------------------------------------------------------------------
// helpers
// ---------------------------------------------------------------------------
// All MMA operands are RNA-rounded to tf32 BEFORE they reach smem, so the
// inner loops feed raw fp32 bit patterns (hardware truncation is then exact).
__device__ __forceinline__ uint32_t ftu(float x) { return __float_as_uint(x); }

__device__ __forceinline__ float rnd_tf32(float x) {
    uint32_t r;
    asm("cvt.rna.tf32.f32 %0, %1;" : "=r"(r) : "f"(x));
    return __uint_as_float(r);
}
__device__ __forceinline__ float ex2(float x) {
    float r;
    asm("ex2.approx.f32 %0, %1;" : "=f"(r) : "f"(x));
    return r;
}
__device__ __forceinline__ void mma8(float* c, const uint32_t* a, const uint32_t* b) {
    asm volatile(
        "mma.sync.aligned.m16n8k8.row.col.f32.tf32.tf32.f32 "
        "{%0,%1,%2,%3}, {%4,%5,%6,%7}, {%8,%9}, {%0,%1,%2,%3};\n"
        : "+f"(c[0]), "+f"(c[1]), "+f"(c[2]), "+f"(c[3])
        : "r"(a[0]), "r"(a[1]), "r"(a[2]), "r"(a[3]), "r"(b[0]), "r"(b[1]));
}
__device__ __forceinline__ uint32_t smaddr(const void* p) {
    return (uint32_t)__cvta_generic_to_shared(p);
}
__device__ __forceinline__ void cp16(uint32_t dst, const void* src) {
    asm volatile("cp.async.ca.shared.global [%0], [%1], 16;\n" :: "r"(dst), "l"(src));
}
__device__ __forceinline__ void cpcommit() {
    asm volatile("cp.async.commit_group;\n");
}
template<int N>
__device__ __forceinline__ void cpwait() {
    asm volatile("cp.async.wait_group %0;\n" :: "n"(N));
}

// ---------------------------------------------------------------------------
// Pre-round: out[i] = tf32_rna(in[i]), vectorized float4.
// ---------------------------------------------------------------------------
__global__ __launch_bounds__(256) void round_tf32_kernel(
    const float4* __restrict__ in, float4* __restrict__ out, int n4)
{
    int i = blockIdx.x * blockDim.x + threadIdx.x;
    if (i < n4) {
        float4 v = in[i];
        v.x = rnd_tf32(v.x); v.y = rnd_tf32(v.y);
        v.z = rnd_tf32(v.z); v.w = rnd_tf32(v.w);
        out[i] = v;
    }
}

// ---------------------------------------------------------------------------
// GEMM: Y = X @ W^T + bias.  128x64 block tile (R13-proven), BK=32, now with
// THREE-stage cp.async pipeline and ONE barrier per k-iter.
// 256 threads = 8 warps (4 M x 2 N), warp tile 32x32.
// split=1: write Y in [B,H,T,D], tf32-rounded; split=0: plain [M,E], fp32.
// smem: 3 stages x (128+64)x36 floats = 82944 B (dynamic).
// ---------------------------------------------------------------------------
#define G_A1  (128 * 36)
#define G_B1  (64 * 36)
#define G_STG (G_A1 + G_B1)
__global__ __launch_bounds__(256) void gemm_bias(
    const float* __restrict__ X, const float* __restrict__ W,
    const float* __restrict__ bias, float* __restrict__ Y, int split)
{
    extern __shared__ float sm[];

    const int tid  = threadIdx.x;
    const int warp = tid >> 5, lane = tid & 31;
    const int wm   = warp >> 1, wn = warp & 1;
    const int g    = lane >> 2, t = lane & 3;
    const int m0   = blockIdx.x * 128;
    const int n0   = blockIdx.y * 64;

    auto issue = [&](int k0, int stg) {
        const float* Ag = X + (size_t)m0 * E_DIM + k0;
        const float* Bg = W + (size_t)n0 * E_DIM + k0;
        float* dA = sm + stg * G_STG;
        float* dB = dA + G_A1;
#pragma unroll
        for (int i = 0; i < 4; i++) {
            int idx = tid + i * 256;          // 0..1023  (128 rows x 8 float4)
            int r = idx >> 3, c4 = idx & 7;
            cp16(smaddr(dA + r * 36 + c4 * 4), Ag + (size_t)r * E_DIM + c4 * 4);
        }
#pragma unroll
        for (int i = 0; i < 2; i++) {
            int idx = tid + i * 256;          // 0..511   (64 rows x 8 float4)
            int r = idx >> 3, c4 = idx & 7;
            cp16(smaddr(dB + r * 36 + c4 * 4), Bg + (size_t)r * E_DIM + c4 * 4);
        }
        cpcommit();
    };

    float acc[2][4][4];
#pragma unroll
    for (int i = 0; i < 2; i++)
#pragma unroll
        for (int j = 0; j < 4; j++)
#pragma unroll
            for (int r = 0; r < 4; r++) acc[i][j][r] = 0.f;

    issue(0, 0);
    issue(32, 1);

    for (int ks = 0; ks < 32; ks++) {
        // Need group ks complete. For ks<30 one newer group may stay pending.
        if (ks < 30) { cpwait<1>(); } else { cpwait<0>(); }
        __syncthreads();              // publishes stage ks%3; also fences the
                                      // stage about to be overwritten below
        if (ks + 2 < 32) issue((ks + 2) * 32, (ks + 2) % 3);

        const float* A  = sm + (ks % 3) * G_STG;
        const float* Bt = A + G_A1;

#pragma unroll
        for (int kk = 0; kk < 32; kk += 8) {
            uint32_t a[2][4], b[4][2];
#pragma unroll
            for (int mt = 0; mt < 2; mt++) {
                int row = wm * 32 + mt * 16;
                a[mt][0] = ftu(A[(row + g)     * 36 + kk + t]);
                a[mt][1] = ftu(A[(row + 8 + g) * 36 + kk + t]);
                a[mt][2] = ftu(A[(row + g)     * 36 + kk + t + 4]);
                a[mt][3] = ftu(A[(row + 8 + g) * 36 + kk + t + 4]);
            }
#pragma unroll
            for (int nt = 0; nt < 4; nt++) {
                int col = wn * 32 + nt * 8 + g;
                b[nt][0] = ftu(Bt[col * 36 + kk + t]);
                b[nt][1] = ftu(Bt[col * 36 + kk + t + 4]);
            }
#pragma unroll
            for (int mt = 0; mt < 2; mt++)
#pragma unroll
                for (int nt = 0; nt < 4; nt++)
                    mma8(acc[mt][nt], a[mt], b[nt]);
        }
    }

    // Epilogue: bias + writeout (split outputs rounded for downstream MMAs)
#pragma unroll
    for (int mt = 0; mt < 2; mt++) {
#pragma unroll
        for (int nt = 0; nt < 4; nt++) {
            int mrow = m0 + wm * 32 + mt * 16 + g;
            int ncol = n0 + wn * 32 + nt * 8 + 2 * t;
            float b0 = bias[ncol], b1 = bias[ncol + 1];
            float v00 = acc[mt][nt][0] + b0, v01 = acc[mt][nt][1] + b1;
            float v10 = acc[mt][nt][2] + b0, v11 = acc[mt][nt][3] + b1;
            if (!split) {
                float* p0 = Y + (size_t)mrow * E_DIM + ncol;
                float* p1 = Y + (size_t)(mrow + 8) * E_DIM + ncol;
                p0[0] = v00; p0[1] = v01;
                p1[0] = v10; p1[1] = v11;
            } else {
                int h = ncol >> 6, d = ncol & 63;
                int bb = mrow >> 11, tt = mrow & 2047;
                size_t o0 = ((size_t)(bb * NH + h) * T_SEQ + tt) * HD + d;
                size_t o1 = o0 + 8 * HD;
                Y[o0] = rnd_tf32(v00); Y[o0 + 1] = rnd_tf32(v01);
                Y[o1] = rnd_tf32(v10); Y[o1 + 1] = rnd_tf32(v11);
            }
        }
    }
}

// ---------------------------------------------------------------------------
// Flash attention: grid (T/64, B*H) = (32, 64), 128 threads (4 warps) —
// the R13-measured structure. Each warp owns 16 query rows; block = 64
// queries x all 2048 keys. K/V streamed in 32-key tiles, double-buffered
// via cp.async; ONE barrier per tile. Softmax: scale folded into ex2 via
// FFMA; warp-vote skip of the o-rescale when the running max is unchanged.
// smem: sQ[64][68] + sK[2][32][68] + sV[2][32][72] = 53248 B (dynamic).
// ---------------------------------------------------------------------------
#define A_SQ  (64 * 68)
#define A_SKB (32 * 68)
#define A_SVB (32 * 72)
__global__ __launch_bounds__(128) void attn_kernel(
    const float* __restrict__ Q, const float* __restrict__ K,
    const float* __restrict__ V, float* __restrict__ O)
{
    extern __shared__ float sm[];
    float* sQ = sm;                     // [64][68]; reused as P scratch
    float* sK = sm + A_SQ;              // [2][32][68]
    float* sV = sK + 2 * A_SKB;         // [2][32][72]

    const int tid  = threadIdx.x;
    const int warp = tid >> 5, lane = tid & 31;
    const int g    = lane >> 2, t = lane & 3;
    const int q0   = blockIdx.x * 64;
    const int bh   = blockIdx.y;

    const float* Qb = Q + ((size_t)bh * T_SEQ + q0) * HD;
    const float* Kb = K + (size_t)bh * T_SEQ * HD;
    const float* Vb = V + (size_t)bh * T_SEQ * HD;

    auto issueKV = [&](int j, int buf) {
        const float* Kg = Kb + (size_t)j * 32 * HD;
        const float* Vg = Vb + (size_t)j * 32 * HD;
        float* dK = sK + buf * A_SKB;
        float* dV = sV + buf * A_SVB;
#pragma unroll
        for (int i = 0; i < 4; i++) {
            int idx = tid + i * 128;          // 0..511  (32 rows x 16 float4)
            int r = idx >> 4, c4 = idx & 15;
            cp16(smaddr(dK + r * 68 + c4 * 4), Kg + r * HD + c4 * 4);
            cp16(smaddr(dV + r * 72 + c4 * 4), Vg + r * HD + c4 * 4);
        }
        cpcommit();
    };

    // Stage Q (group 0), then KV tile 0 (group 1)
#pragma unroll
    for (int i = 0; i < 8; i++) {
        int idx = tid + i * 128;              // 0..1023 (64 rows x 16 float4)
        int r = idx >> 4, c4 = idx & 15;
        cp16(smaddr(sQ + r * 68 + c4 * 4), Qb + r * HD + c4 * 4);
    }
    cpcommit();
    issueKV(0, 0);
    cpwait<1>();          // Q complete (KV0 may still be in flight)
    __syncthreads();

    // Cache Q A-frags in registers (8 k-steps x 4 regs); sQ free afterwards.
    uint32_t qa[8][4];
    {
        int row = warp * 16;
#pragma unroll
        for (int kd = 0; kd < 8; kd++) {
            qa[kd][0] = ftu(sQ[(row + g)     * 68 + kd * 8 + t]);
            qa[kd][1] = ftu(sQ[(row + 8 + g) * 68 + kd * 8 + t]);
            qa[kd][2] = ftu(sQ[(row + g)     * 68 + kd * 8 + t + 4]);
            qa[kd][3] = ftu(sQ[(row + 8 + g) * 68 + kd * 8 + t + 4]);
        }
    }
    // Per-warp P scratch carved out of the (now dead) sQ region.
    float* sP = sQ + warp * (16 * 36);   // [16][36], 4 warps -> 2304 floats

    float m0v = -1e30f, m1v = -1e30f;    // running RAW max (unscaled)
    float l0 = 0.f, l1 = 0.f;
    float o[8][4];
#pragma unroll
    for (int df = 0; df < 8; df++)
#pragma unroll
        for (int r = 0; r < 4; r++) o[df][r] = 0.f;

    const float SC = 0.125f * 1.44269504088896f;   // 1/sqrt(64) * log2(e)

    for (int j = 0; j < T_SEQ / 32; j++) {
        cpwait<0>();          // current KV tile complete
        __syncthreads();      // publish it; also fences buffer overwritten below
                              // (j=0: orders qa loads before first sP store)
        if (j + 1 < T_SEQ / 32) issueKV(j + 1, (j + 1) & 1);

        const float* Kt = sK + (j & 1) * A_SKB;
        const float* Vt = sV + (j & 1) * A_SVB;

        // ---- S = Q K^T : 16 q-rows x 32 keys, k-dim 64 (raw scores) ----
        float s[4][4];
#pragma unroll
        for (int nt = 0; nt < 4; nt++)
#pragma unroll
            for (int r = 0; r < 4; r++) s[nt][r] = 0.f;

#pragma unroll
        for (int kd = 0; kd < 8; kd++) {
#pragma unroll
            for (int nt = 0; nt < 4; nt++) {
                uint32_t b[2];
                b[0] = ftu(Kt[(nt * 8 + g) * 68 + kd * 8 + t]);
                b[1] = ftu(Kt[(nt * 8 + g) * 68 + kd * 8 + t + 4]);
                mma8(s[nt], qa[kd], b);
            }
        }

        // ---- online softmax (base-2, scale folded into ex2 via FFMA) ----
        float mx0 = -1e30f, mx1 = -1e30f;
#pragma unroll
        for (int nt = 0; nt < 4; nt++) {
            mx0 = fmaxf(mx0, fmaxf(s[nt][0], s[nt][1]));
            mx1 = fmaxf(mx1, fmaxf(s[nt][2], s[nt][3]));
        }
        mx0 = fmaxf(mx0, __shfl_xor_sync(0xffffffffu, mx0, 1));
        mx0 = fmaxf(mx0, __shfl_xor_sync(0xffffffffu, mx0, 2));
        mx1 = fmaxf(mx1, __shfl_xor_sync(0xffffffffu, mx1, 1));
        mx1 = fmaxf(mx1, __shfl_xor_sync(0xffffffffu, mx1, 2));

        float mn0 = fmaxf(m0v, mx0), mn1 = fmaxf(m1v, mx1);
        bool nochange = (mn0 == m0v) && (mn1 == m1v);
        bool allsame  = __all_sync(0xffffffffu, nochange);
        float c0 = mn0 * SC, c1 = mn1 * SC;

        float rs0 = 0.f, rs1 = 0.f;
#pragma unroll
        for (int nt = 0; nt < 4; nt++) {
            s[nt][0] = ex2(fmaf(s[nt][0], SC, -c0));
            s[nt][1] = ex2(fmaf(s[nt][1], SC, -c0));
            s[nt][2] = ex2(fmaf(s[nt][2], SC, -c1));
            s[nt][3] = ex2(fmaf(s[nt][3], SC, -c1));
            rs0 += s[nt][0] + s[nt][1];
            rs1 += s[nt][2] + s[nt][3];
        }
        rs0 += __shfl_xor_sync(0xffffffffu, rs0, 1);
        rs0 += __shfl_xor_sync(0xffffffffu, rs0, 2);
        rs1 += __shfl_xor_sync(0xffffffffu, rs1, 1);
        rs1 += __shfl_xor_sync(0xffffffffu, rs1, 2);

        if (allsame) {
            // alpha == 1 exactly: no rescale needed
            l0 += rs0;  l1 += rs1;
        } else {
            float al0 = ex2(fmaf(m0v, SC, -c0));   // m0v=-1e30 -> 0 (first tile)
            float al1 = ex2(fmaf(m1v, SC, -c1));
            l0 = l0 * al0 + rs0;  l1 = l1 * al1 + rs1;
            m0v = mn0;            m1v = mn1;
#pragma unroll
            for (int df = 0; df < 8; df++) {
                o[df][0] *= al0; o[df][1] *= al0;
                o[df][2] *= al1; o[df][3] *= al1;
            }
        }

        // ---- P round-trip through per-warp smem (C-frag -> A-frag),
        //      RNA-rounded once here so the MMA feed below is exact tf32 ----
#pragma unroll
        for (int nt = 0; nt < 4; nt++) {
            sP[g       * 36 + nt * 8 + 2 * t]     = rnd_tf32(s[nt][0]);
            sP[g       * 36 + nt * 8 + 2 * t + 1] = rnd_tf32(s[nt][1]);
            sP[(g + 8) * 36 + nt * 8 + 2 * t]     = rnd_tf32(s[nt][2]);
            sP[(g + 8) * 36 + nt * 8 + 2 * t + 1] = rnd_tf32(s[nt][3]);
        }
        __syncwarp();

        // ---- O += P @ V : 16 x 64, k-dim 32 keys ----
#pragma unroll
        for (int kk = 0; kk < 4; kk++) {
            uint32_t pa[4];
            pa[0] = ftu(sP[g       * 36 + kk * 8 + t]);
            pa[1] = ftu(sP[(g + 8) * 36 + kk * 8 + t]);
            pa[2] = ftu(sP[g       * 36 + kk * 8 + t + 4]);
            pa[3] = ftu(sP[(g + 8) * 36 + kk * 8 + t + 4]);
#pragma unroll
            for (int df = 0; df < 8; df++) {
                uint32_t b[2];
                b[0] = ftu(Vt[(kk * 8 + t)     * 72 + df * 8 + g]);
                b[1] = ftu(Vt[(kk * 8 + t + 4) * 72 + df * 8 + g]);
                mma8(o[df], pa, b);
            }
        }
    }

    // ---- epilogue: normalize, round for the final GEMM, write [B,T,E] ----
    float inv0 = 1.f / l0, inv1 = 1.f / l1;
    int bb = bh >> 4, h = bh & 15;
    int r0 = q0 + warp * 16 + g;
#pragma unroll
    for (int df = 0; df < 8; df++) {
        int d = df * 8 + 2 * t;
        size_t base0 = ((size_t)bb * T_SEQ + r0) * E_DIM + h * HD + d;
        size_t base1 = base0 + (size_t)8 * E_DIM;
        O[base0]     = rnd_tf32(o[df][0] * inv0);
        O[base0 + 1] = rnd_tf32(o[df][1] * inv0);
        O[base1]     = rnd_tf32(o[df][2] * inv1);
        O[base1 + 1] = rnd_tf32(o[df][3] * inv1);
    }
}

// ---------------------------------------------------------------------------
// Launcher
// ---------------------------------------------------------------------------
#define GEMM_SMEM  (3 * G_STG * 4)                       // 82944 B
#define ATTN_SMEM  ((A_SQ + 2 * A_SKB + 2 * A_SVB) * 4)  // 53248 B

extern "C" void kernel_launch(void* const* d_in, const int* in_sizes, int n_in,
                              void* d_out, int out_size)
{
    const float* x  = (const float*)d_in[0];
    const float* Wq = (const float*)d_in[1];
    const float* bq = (const float*)d_in[2];
    const float* Wk = (const float*)d_in[3];
    const float* bk = (const float*)d_in[4];
    const float* Wv = (const float*)d_in[5];
    const float* bv = (const float*)d_in[6];
    const float* Wo = (const float*)d_in[7];
    const float* bo = (const float*)d_in[8];

    float *q, *k, *v, *ctx, *xr, *wq, *wk, *wv, *wo;
    cudaGetSymbolAddress((void**)&q,   g_q);
    cudaGetSymbolAddress((void**)&k,   g_k);
    cudaGetSymbolAddress((void**)&v,   g_v);
    cudaGetSymbolAddress((void**)&ctx, g_ctx);
    cudaGetSymbolAddress((void**)&xr,  g_x);
    cudaGetSymbolAddress((void**)&wq,  g_wq);
    cudaGetSymbolAddress((void**)&wk,  g_wk);
    cudaGetSymbolAddress((void**)&wv,  g_wv);
    cudaGetSymbolAddress((void**)&wo,  g_wo);

    cudaFuncSetAttribute(gemm_bias, cudaFuncAttributeMaxDynamicSharedMemorySize, GEMM_SMEM);
    cudaFuncSetAttribute(attn_kernel, cudaFuncAttributeMaxDynamicSharedMemorySize, ATTN_SMEM);

    // Pre-round x and weights to tf32 (RNA) so all MMA feeds are exact.
    const int NX4 = (M_TOT * E_DIM) / 4;    // 2,097,152
    const int NW4 = (E_DIM * E_DIM) / 4;    // 262,144
    round_tf32_kernel<<<NX4 / 256, 256>>>((const float4*)x,  (float4*)xr, NX4);
    round_tf32_kernel<<<NW4 / 256, 256>>>((const float4*)Wq, (float4*)wq, NW4);
    round_tf32_kernel<<<NW4 / 256, 256>>>((const float4*)Wk, (float4*)wk, NW4);
    round_tf32_kernel<<<NW4 / 256, 256>>>((const float4*)Wv, (float4*)wv, NW4);
    round_tf32_kernel<<<NW4 / 256, 256>>>((const float4*)Wo, (float4*)wo, NW4);

    dim3 ggrid(M_TOT / 128, E_DIM / 64);    // (64, 16)

    gemm_bias<<<ggrid, 256, GEMM_SMEM>>>(xr, wq, bq, q, 1);
    gemm_bias<<<ggrid, 256, GEMM_SMEM>>>(xr, wk, bk, k, 1);
    gemm_bias<<<ggrid, 256, GEMM_SMEM>>>(xr, wv, bv, v, 1);

    attn_kernel<<<dim3(T_SEQ / 64, B_SZ * NH), 128, ATTN_SMEM>>>(q, k, v, ctx);

    gemm_bias<<<ggrid, 256, GEMM_SMEM>>>(ctx, wo, bo, (float*)d_out, 0);
}

// round 16
// speedup vs baseline: 1.0967x; 1.0967x over previous
#include <cuda_runtime.h>
#include <cstdint>

// Problem constants (fixed-shape problem)
#define B_SZ   4
#define T_SEQ  2048
#define E_DIM  1024
#define NH     16
#define HD     64
#define M_TOT  (B_SZ * T_SEQ)   // 8192

// ---------------------------------------------------------------------------
// Scratch (allocation-free rule: __device__ globals)
// ---------------------------------------------------------------------------
__device__ float g_q[(size_t)M_TOT * E_DIM];    // [B,H,T,D] (tf32-rounded)
__device__ float g_k[(size_t)M_TOT * E_DIM];    // [B,H,T,D] (tf32-rounded)
__device__ float g_v[(size_t)M_TOT * E_DIM];    // [B,H,T,D] (tf32-rounded)
__device__ float g_ctx[(size_t)M_TOT * E_DIM];  // [B,T,E]   (tf32-rounded)
__device__ float g_x [(size_t)M_TOT * E_DIM];   // tf32-rounded copy of x
__device__ float g_wq[(size_t)E_DIM * E_DIM];   // tf32-rounded weights
__device__ float g_wk[(size_t)E_DIM * E_DIM];
__device__ float g_wv[(size_t)E_DIM * E_DIM];
__device__ float g_wo[(size_t)E_DIM * E_DIM];

// ---------------------------------------------------------------------------
// helpers
// ---------------------------------------------------------------------------
// All MMA operands are RNA-rounded to tf32 BEFORE they reach smem, so the
// inner loops feed raw fp32 bit patterns (hardware truncation is then exact).
__device__ __forceinline__ uint32_t ftu(float x) { return __float_as_uint(x); }

__device__ __forceinline__ float rnd_tf32(float x) {
    uint32_t r;
    asm("cvt.rna.tf32.f32 %0, %1;" : "=r"(r) : "f"(x));
    return __uint_as_float(r);
}
__device__ __forceinline__ float ex2(float x) {
    float r;
    asm("ex2.approx.f32 %0, %1;" : "=f"(r) : "f"(x));
    return r;
}
__device__ __forceinline__ void mma8(float* c, const uint32_t* a, const uint32_t* b) {
    asm volatile(
        "mma.sync.aligned.m16n8k8.row.col.f32.tf32.tf32.f32 "
        "{%0,%1,%2,%3}, {%4,%5,%6,%7}, {%8,%9}, {%0,%1,%2,%3};\n"
        : "+f"(c[0]), "+f"(c[1]), "+f"(c[2]), "+f"(c[3])
        : "r"(a[0]), "r"(a[1]), "r"(a[2]), "r"(a[3]), "r"(b[0]), "r"(b[1]));
}
// ldmatrix x4 (b16 form; for 32-bit data lane l receives the b32 at
// (row l/4, b32-col l%4) of each 8x16B matrix -> exact tf32 frag mapping)
__device__ __forceinline__ void ldsm4(uint32_t* r, uint32_t addr) {
    asm volatile("ldmatrix.sync.aligned.m8n8.x4.shared.b16 {%0,%1,%2,%3}, [%4];\n"
        : "=r"(r[0]), "=r"(r[1]), "=r"(r[2]), "=r"(r[3]) : "r"(addr));
}
__device__ __forceinline__ uint32_t smaddr(const void* p) {
    return (uint32_t)__cvta_generic_to_shared(p);
}
__device__ __forceinline__ void cp16(uint32_t dst, const void* src) {
    asm volatile("cp.async.ca.shared.global [%0], [%1], 16;\n" :: "r"(dst), "l"(src));
}
__device__ __forceinline__ void cpcommit() {
    asm volatile("cp.async.commit_group;\n");
}
template<int N>
__device__ __forceinline__ void cpwait() {
    asm volatile("cp.async.wait_group %0;\n" :: "n"(N));
}

// ---------------------------------------------------------------------------
// Pre-round: out[i] = tf32_rna(in[i]), vectorized float4.
// ---------------------------------------------------------------------------
__global__ __launch_bounds__(256) void round_tf32_kernel(
    const float4* __restrict__ in, float4* __restrict__ out, int n4)
{
    int i = blockIdx.x * blockDim.x + threadIdx.x;
    if (i < n4) {
        float4 v = in[i];
        v.x = rnd_tf32(v.x); v.y = rnd_tf32(v.y);
        v.z = rnd_tf32(v.z); v.w = rnd_tf32(v.w);
        out[i] = v;
    }
}

// ---------------------------------------------------------------------------
// GEMM: Y = X @ W^T + bias.  128x64 block tile, BK=32, 3-stage cp.async,
// one barrier per k-iter, fragment loads via ldmatrix.x4 (16 LDSM/iter/warp
// instead of 64 LDS). 256 threads = 8 warps (4 M x 2 N), warp tile 32x32.
// split=1: write Y in [B,H,T,D], tf32-rounded; split=0: plain [M,E], fp32.
// smem: 3 stages x (128+64)x36 floats = 82944 B (dynamic).
// ---------------------------------------------------------------------------
#define G_A1  (128 * 36)
#define G_B1  (64 * 36)
#define G_STG (G_A1 + G_B1)
__global__ __launch_bounds__(256) void gemm_bias(
    const float* __restrict__ X, const float* __restrict__ W,
    const float* __restrict__ bias, float* __restrict__ Y, int split)
{
    extern __shared__ float sm[];

    const int tid  = threadIdx.x;
    const int warp = tid >> 5, lane = tid & 31;
    const int wm   = warp >> 1, wn = warp & 1;
    const int g    = lane >> 2, t = lane & 3;
    const int m0   = blockIdx.x * 128;
    const int n0   = blockIdx.y * 64;

    auto issue = [&](int k0, int stg) {
        const float* Ag = X + (size_t)m0 * E_DIM + k0;
        const float* Bg = W + (size_t)n0 * E_DIM + k0;
        float* dA = sm + stg * G_STG;
        float* dB = dA + G_A1;
#pragma unroll
        for (int i = 0; i < 4; i++) {
            int idx = tid + i * 256;          // 0..1023  (128 rows x 8 float4)
            int r = idx >> 3, c4 = idx & 7;
            cp16(smaddr(dA + r * 36 + c4 * 4), Ag + (size_t)r * E_DIM + c4 * 4);
        }
#pragma unroll
        for (int i = 0; i < 2; i++) {
            int idx = tid + i * 256;          // 0..511   (64 rows x 8 float4)
            int r = idx >> 3, c4 = idx & 7;
            cp16(smaddr(dB + r * 36 + c4 * 4), Bg + (size_t)r * E_DIM + c4 * 4);
        }
        cpcommit();
    };

    // Per-lane ldmatrix row addresses (bytes, relative to stage base).
    // A-operand (mtx sel: 0=rows+0/col+0, 1=rows+8/col+0, 2=rows+0/+4, 3=+8/+4)
    const int sel = lane >> 3, rr = lane & 7;
    const int a_ro = ((sel & 1) ? 8 : 0) + rr;
    const int a_co = (sel & 2) ? 4 : 0;
    uint32_t aoff[2];
#pragma unroll
    for (int mt = 0; mt < 2; mt++)
        aoff[mt] = (uint32_t)(((wm * 32 + mt * 16 + a_ro) * 36 + a_co) * 4);
    // B-operand (mtx sel: 0=cols+0/k+0, 1=cols+0/k+4, 2=cols+8/k+0, 3=+8/+4)
    const int b_ro = ((sel & 2) ? 8 : 0) + rr;
    const int b_co = (sel & 1) ? 4 : 0;
    uint32_t boff[2];
#pragma unroll
    for (int p = 0; p < 2; p++)
        boff[p] = (uint32_t)((G_A1 + (wn * 32 + p * 16 + b_ro) * 36 + b_co) * 4);

    const uint32_t sbase = smaddr(sm);

    float acc[2][4][4];
#pragma unroll
    for (int i = 0; i < 2; i++)
#pragma unroll
        for (int j = 0; j < 4; j++)
#pragma unroll
            for (int r = 0; r < 4; r++) acc[i][j][r] = 0.f;

    issue(0, 0);
    issue(32, 1);

    for (int ks = 0; ks < 32; ks++) {
        if (ks < 30) { cpwait<1>(); } else { cpwait<0>(); }
        __syncthreads();              // publishes stage ks%3; also fences the
                                      // stage about to be overwritten below
        if (ks + 2 < 32) issue((ks + 2) * 32, (ks + 2) % 3);

        const uint32_t stg = sbase + (uint32_t)((ks % 3) * (G_STG * 4));

#pragma unroll
        for (int kk = 0; kk < 32; kk += 8) {
            uint32_t a0[4], a1[4], b0[4], b1[4];
            ldsm4(a0, stg + aoff[0] + kk * 4);
            ldsm4(a1, stg + aoff[1] + kk * 4);
            ldsm4(b0, stg + boff[0] + kk * 4);
            ldsm4(b1, stg + boff[1] + kk * 4);
            mma8(acc[0][0], a0, b0);     mma8(acc[0][1], a0, b0 + 2);
            mma8(acc[0][2], a0, b1);     mma8(acc[0][3], a0, b1 + 2);
            mma8(acc[1][0], a1, b0);     mma8(acc[1][1], a1, b0 + 2);
            mma8(acc[1][2], a1, b1);     mma8(acc[1][3], a1, b1 + 2);
        }
    }

    // Epilogue: bias + writeout (split outputs rounded for downstream MMAs)
#pragma unroll
    for (int mt = 0; mt < 2; mt++) {
#pragma unroll
        for (int nt = 0; nt < 4; nt++) {
            int mrow = m0 + wm * 32 + mt * 16 + g;
            int ncol = n0 + wn * 32 + nt * 8 + 2 * t;
            float b0 = bias[ncol], b1 = bias[ncol + 1];
            float v00 = acc[mt][nt][0] + b0, v01 = acc[mt][nt][1] + b1;
            float v10 = acc[mt][nt][2] + b0, v11 = acc[mt][nt][3] + b1;
            if (!split) {
                float* p0 = Y + (size_t)mrow * E_DIM + ncol;
                float* p1 = Y + (size_t)(mrow + 8) * E_DIM + ncol;
                p0[0] = v00; p0[1] = v01;
                p1[0] = v10; p1[1] = v11;
            } else {
                int h = ncol >> 6, d = ncol & 63;
                int bb = mrow >> 11, tt = mrow & 2047;
                size_t o0 = ((size_t)(bb * NH + h) * T_SEQ + tt) * HD + d;
                size_t o1 = o0 + 8 * HD;
                Y[o0] = rnd_tf32(v00); Y[o0 + 1] = rnd_tf32(v01);
                Y[o1] = rnd_tf32(v10); Y[o1 + 1] = rnd_tf32(v11);
            }
        }
    }
}

// ---------------------------------------------------------------------------
// Flash attention: grid (T/64, B*H) = (32, 64), 128 threads (4 warps).
// Each warp owns 16 query rows; block = 64 queries x all 2048 keys.
// K/V streamed in 32-key tiles, double-buffered via cp.async; one barrier
// per tile. K and P fragments loaded via ldmatrix.x4; V stays scalar LDS
// (transposed access). Softmax: base-2 with scale folded into FFMA + warp-
// vote rescale skip.
// smem: sQ[64][68] + sK[2][32][68] + sV[2][32][72] = 53248 B (dynamic).
// ---------------------------------------------------------------------------
#define A_SQ  (64 * 68)
#define A_SKB (32 * 68)
#define A_SVB (32 * 72)
__global__ __launch_bounds__(128) void attn_kernel(
    const float* __restrict__ Q, const float* __restrict__ K,
    const float* __restrict__ V, float* __restrict__ O)
{
    extern __shared__ float sm[];
    float* sQ = sm;                     // [64][68]; reused as P scratch
    float* sK = sm + A_SQ;              // [2][32][68]
    float* sV = sK + 2 * A_SKB;         // [2][32][72]

    const int tid  = threadIdx.x;
    const int warp = tid >> 5, lane = tid & 31;
    const int g    = lane >> 2, t = lane & 3;
    const int q0   = blockIdx.x * 64;
    const int bh   = blockIdx.y;

    const float* Qb = Q + ((size_t)bh * T_SEQ + q0) * HD;
    const float* Kb = K + (size_t)bh * T_SEQ * HD;
    const float* Vb = V + (size_t)bh * T_SEQ * HD;

    auto issueKV = [&](int j, int buf) {
        const float* Kg = Kb + (size_t)j * 32 * HD;
        const float* Vg = Vb + (size_t)j * 32 * HD;
        float* dK = sK + buf * A_SKB;
        float* dV = sV + buf * A_SVB;
#pragma unroll
        for (int i = 0; i < 4; i++) {
            int idx = tid + i * 128;          // 0..511  (32 rows x 16 float4)
            int r = idx >> 4, c4 = idx & 15;
            cp16(smaddr(dK + r * 68 + c4 * 4), Kg + r * HD + c4 * 4);
            cp16(smaddr(dV + r * 72 + c4 * 4), Vg + r * HD + c4 * 4);
        }
        cpcommit();
    };

    // Stage Q (group 0), then KV tile 0 (group 1)
#pragma unroll
    for (int i = 0; i < 8; i++) {
        int idx = tid + i * 128;              // 0..1023 (64 rows x 16 float4)
        int r = idx >> 4, c4 = idx & 15;
        cp16(smaddr(sQ + r * 68 + c4 * 4), Qb + r * HD + c4 * 4);
    }
    cpcommit();
    issueKV(0, 0);
    cpwait<1>();          // Q complete (KV0 may still be in flight)
    __syncthreads();

    // Cache Q A-frags in registers (8 k-steps x 4 regs); sQ free afterwards.
    uint32_t qa[8][4];
    {
        int row = warp * 16;
#pragma unroll
        for (int kd = 0; kd < 8; kd++) {
            qa[kd][0] = ftu(sQ[(row + g)     * 68 + kd * 8 + t]);
            qa[kd][1] = ftu(sQ[(row + 8 + g) * 68 + kd * 8 + t]);
            qa[kd][2] = ftu(sQ[(row + g)     * 68 + kd * 8 + t + 4]);
            qa[kd][3] = ftu(sQ[(row + 8 + g) * 68 + kd * 8 + t + 4]);
        }
    }
    // Per-warp P scratch carved out of the (now dead) sQ region.
    float* sP = sQ + warp * (16 * 36);   // [16][36], 4 warps -> 2304 floats

    // ldmatrix per-lane offsets
    const int sel = lane >> 3, rr = lane & 7;
    // K (B-operand): sel 0=keys+0/k+0, 1=keys+0/k+4, 2=keys+8/k+0, 3=+8/+4
    const int k_ro = ((sel & 2) ? 8 : 0) + rr;
    const int k_co = (sel & 1) ? 4 : 0;
    uint32_t koff[2];
#pragma unroll
    for (int p = 0; p < 2; p++)
        koff[p] = (uint32_t)(((p * 16 + k_ro) * 68 + k_co) * 4);
    const uint32_t kbase = smaddr(sm) + A_SQ * 4;
    // P (A-operand): sel 0=rows+0/k+0, 1=rows+8/k+0, 2=rows+0/+4, 3=+8/+4
    const int p_ro = ((sel & 1) ? 8 : 0) + rr;
    const int p_co = (sel & 2) ? 4 : 0;
    const uint32_t pbase = smaddr(sP) + (uint32_t)((p_ro * 36 + p_co) * 4);

    float m0v = -1e30f, m1v = -1e30f;    // running RAW max (unscaled)
    float l0 = 0.f, l1 = 0.f;
    float o[8][4];
#pragma unroll
    for (int df = 0; df < 8; df++)
#pragma unroll
        for (int r = 0; r < 4; r++) o[df][r] = 0.f;

    const float SC = 0.125f * 1.44269504088896f;   // 1/sqrt(64) * log2(e)

    for (int j = 0; j < T_SEQ / 32; j++) {
        cpwait<0>();          // current KV tile complete
        __syncthreads();      // publish it; also fences buffer overwritten below
                              // (j=0: orders qa loads before first sP store)
        if (j + 1 < T_SEQ / 32) issueKV(j + 1, (j + 1) & 1);

        const uint32_t kstg = kbase + (uint32_t)((j & 1) * (A_SKB * 4));
        const float* Vt = sV + (j & 1) * A_SVB;

        // ---- S = Q K^T : 16 q-rows x 32 keys, k-dim 64 (raw scores) ----
        float s[4][4];
#pragma unroll
        for (int nt = 0; nt < 4; nt++)
#pragma unroll
            for (int r = 0; r < 4; r++) s[nt][r] = 0.f;

#pragma unroll
        for (int kd = 0; kd < 8; kd++) {
            uint32_t b0[4], b1[4];
            ldsm4(b0, kstg + koff[0] + kd * 32);
            ldsm4(b1, kstg + koff[1] + kd * 32);
            mma8(s[0], qa[kd], b0);      mma8(s[1], qa[kd], b0 + 2);
            mma8(s[2], qa[kd], b1);      mma8(s[3], qa[kd], b1 + 2);
        }

        // ---- online softmax (base-2, scale folded into ex2 via FFMA) ----
        float mx0 = -1e30f, mx1 = -1e30f;
#pragma unroll
        for (int nt = 0; nt < 4; nt++) {
            mx0 = fmaxf(mx0, fmaxf(s[nt][0], s[nt][1]));
            mx1 = fmaxf(mx1, fmaxf(s[nt][2], s[nt][3]));
        }
        mx0 = fmaxf(mx0, __shfl_xor_sync(0xffffffffu, mx0, 1));
        mx0 = fmaxf(mx0, __shfl_xor_sync(0xffffffffu, mx0, 2));
        mx1 = fmaxf(mx1, __shfl_xor_sync(0xffffffffu, mx1, 1));
        mx1 = fmaxf(mx1, __shfl_xor_sync(0xffffffffu, mx1, 2));

        float mn0 = fmaxf(m0v, mx0), mn1 = fmaxf(m1v, mx1);
        bool nochange = (mn0 == m0v) && (mn1 == m1v);
        bool allsame  = __all_sync(0xffffffffu, nochange);
        float c0 = mn0 * SC, c1 = mn1 * SC;

        float rs0 = 0.f, rs1 = 0.f;
#pragma unroll
        for (int nt = 0; nt < 4; nt++) {
            s[nt][0] = ex2(fmaf(s[nt][0], SC, -c0));
            s[nt][1] = ex2(fmaf(s[nt][1], SC, -c0));
            s[nt][2] = ex2(fmaf(s[nt][2], SC, -c1));
            s[nt][3] = ex2(fmaf(s[nt][3], SC, -c1));
            rs0 += s[nt][0] + s[nt][1];
            rs1 += s[nt][2] + s[nt][3];
        }
        rs0 += __shfl_xor_sync(0xffffffffu, rs0, 1);
        rs0 += __shfl_xor_sync(0xffffffffu, rs0, 2);
        rs1 += __shfl_xor_sync(0xffffffffu, rs1, 1);
        rs1 += __shfl_xor_sync(0xffffffffu, rs1, 2);

        if (allsame) {
            // alpha == 1 exactly: no rescale needed
            l0 += rs0;  l1 += rs1;
        } else {
            float al0 = ex2(fmaf(m0v, SC, -c0));   // m0v=-1e30 -> 0 (first tile)
            float al1 = ex2(fmaf(m1v, SC, -c1));
            l0 = l0 * al0 + rs0;  l1 = l1 * al1 + rs1;
            m0v = mn0;            m1v = mn1;
#pragma unroll
            for (int df = 0; df < 8; df++) {
                o[df][0] *= al0; o[df][1] *= al0;
                o[df][2] *= al1; o[df][3] *= al1;
            }
        }

        // ---- P round-trip through per-warp smem (C-frag -> A-frag),
        //      RNA-rounded once here so the MMA feed below is exact tf32 ----
#pragma unroll
        for (int nt = 0; nt < 4; nt++) {
            sP[g       * 36 + nt * 8 + 2 * t]     = rnd_tf32(s[nt][0]);
            sP[g       * 36 + nt * 8 + 2 * t + 1] = rnd_tf32(s[nt][1]);
            sP[(g + 8) * 36 + nt * 8 + 2 * t]     = rnd_tf32(s[nt][2]);
            sP[(g + 8) * 36 + nt * 8 + 2 * t + 1] = rnd_tf32(s[nt][3]);
        }
        __syncwarp();

        // ---- O += P @ V : 16 x 64, k-dim 32 keys ----
#pragma unroll
        for (int kk = 0; kk < 4; kk++) {
            uint32_t pa[4];
            ldsm4(pa, pbase + kk * 32);
#pragma unroll
            for (int df = 0; df < 8; df++) {
                uint32_t b[2];
                b[0] = ftu(Vt[(kk * 8 + t)     * 72 + df * 8 + g]);
                b[1] = ftu(Vt[(kk * 8 + t + 4) * 72 + df * 8 + g]);
                mma8(o[df], pa, b);
            }
        }
    }

    // ---- epilogue: normalize, round for the final GEMM, write [B,T,E] ----
    float inv0 = 1.f / l0, inv1 = 1.f / l1;
    int bb = bh >> 4, h = bh & 15;
    int r0 = q0 + warp * 16 + g;
#pragma unroll
    for (int df = 0; df < 8; df++) {
        int d = df * 8 + 2 * t;
        size_t base0 = ((size_t)bb * T_SEQ + r0) * E_DIM + h * HD + d;
        size_t base1 = base0 + (size_t)8 * E_DIM;
        O[base0]     = rnd_tf32(o[df][0] * inv0);
        O[base0 + 1] = rnd_tf32(o[df][1] * inv0);
        O[base1]     = rnd_tf32(o[df][2] * inv1);
        O[base1 + 1] = rnd_tf32(o[df][3] * inv1);
    }
}

// ---------------------------------------------------------------------------
// Launcher
// ---------------------------------------------------------------------------
#define GEMM_SMEM  (3 * G_STG * 4)                       // 82944 B
#define ATTN_SMEM  ((A_SQ + 2 * A_SKB + 2 * A_SVB) * 4)  // 53248 B

extern "C" void kernel_launch(void* const* d_in, const int* in_sizes, int n_in,
                              void* d_out, int out_size)
{
    const float* x  = (const float*)d_in[0];
    const float* Wq = (const float*)d_in[1];
    const float* bq = (const float*)d_in[2];
    const float* Wk = (const float*)d_in[3];
    const float* bk = (const float*)d_in[4];
    const float* Wv = (const float*)d_in[5];
    const float* bv = (const float*)d_in[6];
    const float* Wo = (const float*)d_in[7];
    const float* bo = (const float*)d_in[8];

    float *q, *k, *v, *ctx, *xr, *wq, *wk, *wv, *wo;
    cudaGetSymbolAddress((void**)&q,   g_q);
    cudaGetSymbolAddress((void**)&k,   g_k);
    cudaGetSymbolAddress((void**)&v,   g_v);
    cudaGetSymbolAddress((void**)&ctx, g_ctx);
    cudaGetSymbolAddress((void**)&xr,  g_x);
    cudaGetSymbolAddress((void**)&wq,  g_wq);
    cudaGetSymbolAddress((void**)&wk,  g_wk);
    cudaGetSymbolAddress((void**)&wv,  g_wv);
    cudaGetSymbolAddress((void**)&wo,  g_wo);

    cudaFuncSetAttribute(gemm_bias, cudaFuncAttributeMaxDynamicSharedMemorySize, GEMM_SMEM);
    cudaFuncSetAttribute(attn_kernel, cudaFuncAttributeMaxDynamicSharedMemorySize, ATTN_SMEM);

    // Pre-round x and weights to tf32 (RNA) so all MMA feeds are exact.
    const int NX4 = (M_TOT * E_DIM) / 4;    // 2,097,152
    const int NW4 = (E_DIM * E_DIM) / 4;    // 262,144
    round_tf32_kernel<<<NX4 / 256, 256>>>((const float4*)x,  (float4*)xr, NX4);
    round_tf32_kernel<<<NW4 / 256, 256>>>((const float4*)Wq, (float4*)wq, NW4);
    round_tf32_kernel<<<NW4 / 256, 256>>>((const float4*)Wk, (float4*)wk, NW4);
    round_tf32_kernel<<<NW4 / 256, 256>>>((const float4*)Wv, (float4*)wv, NW4);
    round_tf32_kernel<<<NW4 / 256, 256>>>((const float4*)Wo, (float4*)wo, NW4);

    dim3 ggrid(M_TOT / 128, E_DIM / 64);    // (64, 16)

    gemm_bias<<<ggrid, 256, GEMM_SMEM>>>(xr, wq, bq, q, 1);
    gemm_bias<<<ggrid, 256, GEMM_SMEM>>>(xr, wk, bk, k, 1);
    gemm_bias<<<ggrid, 256, GEMM_SMEM>>>(xr, wv, bv, v, 1);

    attn_kernel<<<dim3(T_SEQ / 64, B_SZ * NH), 128, ATTN_SMEM>>>(q, k, v, ctx);

    gemm_bias<<<ggrid, 256, GEMM_SMEM>>>(ctx, wo, bo, (float*)d_out, 0);
}